// round 1
// baseline (speedup 1.0000x reference)
#include <cuda_runtime.h>

// ---------------------------------------------------------------------------
// StepWiseMLPAutoEncoder: fp32 baseline
//   encoder: controls = (relu(comb @ We1 + be1)) @ We2 + be2   [fully parallel]
//   decoder: 256-step recurrence, 2 kernels per step
// ---------------------------------------------------------------------------

#define BATCH 64
#define SS    1024      // stft buckets
#define TT    256       // sequence length
#define HH    64        // hidden
#define EM    1056      // encoder mid
#define DM    1056      // decoder mid
#define KC    2048      // 2*SS (comb width)
#define KD1   1088      // SS + HH
#define MROWS (BATCH*TT) // 16384

// scratch (device globals: no allocation allowed)
__device__ float g_xT[BATCH * TT * SS];          // x transposed to [B,T,S]
__device__ float g_h1[(size_t)MROWS * EM];       // encoder hidden
__device__ float g_ctrl[MROWS * HH];             // controls [B,T,H]
__device__ float g_hd[BATCH * DM];               // decoder hidden (per step)
__device__ float g_sbuf[2][BATCH * SS];          // ping-pong prev_stft

// ---------------------------------------------------------------------------
// x[b,s,t] -> xT[b,t,s]
// ---------------------------------------------------------------------------
__global__ void transpose_x_kernel(const float* __restrict__ x)
{
    __shared__ float tile[32][33];
    int b  = blockIdx.z;
    int t0 = blockIdx.x * 32;
    int s0 = blockIdx.y * 32;
    const float* xb  = x    + (size_t)b * SS * TT;
    float*       xTb = g_xT + (size_t)b * TT * SS;
    int tx = threadIdx.x, ty = threadIdx.y;
#pragma unroll
    for (int j = 0; j < 32; j += 8)
        tile[ty + j][tx] = xb[(s0 + ty + j) * TT + t0 + tx];
    __syncthreads();
#pragma unroll
    for (int j = 0; j < 32; j += 8)
        xTb[(t0 + ty + j) * SS + s0 + tx] = tile[tx][ty + j];
}

// ---------------------------------------------------------------------------
// Encoder GEMM, 64x64 tile, BK=16, 256 threads, 4x4 per thread.
// MODE 0: A = comb (gathered from g_xT), C = relu(A@We1+be1) -> g_h1
// MODE 1: A = g_h1,                      C = A@We2+be2       -> g_ctrl
// ---------------------------------------------------------------------------
template<int MODE>
__global__ __launch_bounds__(256) void enc_gemm_kernel(
    const float* __restrict__ Bmat, const float* __restrict__ bias)
{
    constexpr int N = (MODE == 0) ? EM : HH;
    constexpr int K = (MODE == 0) ? KC : EM;

    __shared__ float As[16][64];
    __shared__ float Bs[16][64];

    int tid  = threadIdx.x;
    int arow = tid >> 2;
    int acol = (tid & 3) * 4;
    int tn   = tid & 15;
    int tm   = tid >> 4;
    int n0   = blockIdx.x * 64;
    int r0   = blockIdx.y * 64;

    float acc[4][4] = {};

    int r = r0 + arow;
    const float* aprev = nullptr;   // MODE 0: prev-frame half
    const float* acur  = nullptr;   // MODE 0: current-frame half / MODE 1: row
    if (MODE == 0) {
        int bb = r >> 8;           // TT = 256
        int t  = r & 255;
        acur  = g_xT + ((size_t)((bb << 8) + t)) * SS;
        aprev = (t > 0) ? (acur - SS) : nullptr;
    } else {
        acur = g_h1 + (size_t)r * K;
    }

    for (int kc = 0; kc < K; kc += 16) {
        // --- load A tile (one float4 per thread) ---
        float4 av = make_float4(0.f, 0.f, 0.f, 0.f);
        int kg = kc + acol;
        if (MODE == 0) {
            if (kg < SS) {
                if (aprev) av = *(const float4*)(aprev + kg);
            } else {
                av = *(const float4*)(acur + kg - SS);
            }
        } else {
            av = *(const float4*)(acur + kg);
        }
        As[acol + 0][arow] = av.x;
        As[acol + 1][arow] = av.y;
        As[acol + 2][arow] = av.z;
        As[acol + 3][arow] = av.w;

        // --- load B tile ---
#pragma unroll
        for (int it = 0; it < 4; it++) {
            int k = (tid >> 6) + it * 4;
            int n = tid & 63;
            int ng = n0 + n;
            float v = 0.f;
            if (ng < N) v = Bmat[(size_t)(kc + k) * N + ng];
            Bs[k][n] = v;
        }
        __syncthreads();

#pragma unroll
        for (int kk = 0; kk < 16; kk++) {
            float4 a4 = *(const float4*)&As[kk][tm * 4];
            float4 b4 = *(const float4*)&Bs[kk][tn * 4];
            float aa[4] = {a4.x, a4.y, a4.z, a4.w};
            float bb[4] = {b4.x, b4.y, b4.z, b4.w};
#pragma unroll
            for (int i = 0; i < 4; i++)
#pragma unroll
                for (int j = 0; j < 4; j++)
                    acc[i][j] += aa[i] * bb[j];
        }
        __syncthreads();
    }

    // --- epilogue ---
#pragma unroll
    for (int j = 0; j < 4; j++) {
        int ng = n0 + tn * 4 + j;
        if (ng < N) {
            float bv = bias[ng];
#pragma unroll
            for (int i = 0; i < 4; i++) {
                int rr = r0 + tm * 4 + i;
                float v = acc[i][j] + bv;
                if (MODE == 0)
                    g_h1[(size_t)rr * EM + ng] = fmaxf(v, 0.f);
                else
                    g_ctrl[rr * HH + ng] = v;
            }
        }
    }
}

// ---------------------------------------------------------------------------
// Decoder layer 1 (one timestep):
//   g_hd[64,1056] = relu( [ctrl_t | prev] @ Wd1 + bd1 )
// Block: 128 threads, computes 64(m) x 8(n) tile. grid = 132.
// ---------------------------------------------------------------------------
__global__ __launch_bounds__(128) void dec_layer1_kernel(
    int t, const float* __restrict__ Wd1, const float* __restrict__ bd1)
{
    __shared__ float s_a[32 * 66];   // [kk][m], stride 66 (conflict-light)
    __shared__ float s_w[32][8];

    int tid = threadIdx.x;
    int tx  = tid & 7;
    int ty  = tid >> 3;              // 0..15, handles 4 m each
    int n0  = blockIdx.x * 8;
    const float* sprev = g_sbuf[t & 1];

    float acc[4] = {0.f, 0.f, 0.f, 0.f};

    for (int k0 = 0; k0 < KD1; k0 += 32) {
        // load s_a: inp[m, k0+kk]  (coalesced 128B per m-row)
#pragma unroll
        for (int i = 0; i < 16; i++) {
            int idx = i * 128 + tid;
            int m   = idx >> 5;
            int kk  = idx & 31;
            int kg  = k0 + kk;
            float v = (kg < HH) ? g_ctrl[(m * TT + t) * HH + kg]
                                : sprev[m * SS + kg - HH];
            s_a[kk * 66 + m] = v;
        }
        // load s_w
        {
            int kk = tid >> 2;
            int n2 = (tid & 3) * 2;
            const float* wp = Wd1 + (size_t)(k0 + kk) * DM + n0 + n2;
            s_w[kk][n2]     = wp[0];
            s_w[kk][n2 + 1] = wp[1];
        }
        __syncthreads();

#pragma unroll
        for (int kk = 0; kk < 32; kk++) {
            float w = s_w[kk][tx];
            const float* ap = &s_a[kk * 66 + ty * 4];
            float2 a01 = *(const float2*)ap;
            float2 a23 = *(const float2*)(ap + 2);
            acc[0] += a01.x * w;
            acc[1] += a01.y * w;
            acc[2] += a23.x * w;
            acc[3] += a23.y * w;
        }
        __syncthreads();
    }

    int n = n0 + tx;
    float bv = bd1[n];
#pragma unroll
    for (int im = 0; im < 4; im++)
        g_hd[(ty * 4 + im) * DM + n] = fmaxf(acc[im] + bv, 0.f);
}

// ---------------------------------------------------------------------------
// Decoder layer 2 (one timestep):
//   out_t[64,1024] = g_hd @ Wd2 + bd2 ;  written to d_out and next prev buffer
// Block: 128 threads, 64(m) x 8(n). grid = 128.
// ---------------------------------------------------------------------------
__global__ __launch_bounds__(128) void dec_layer2_kernel(
    int t, const float* __restrict__ Wd2, const float* __restrict__ bd2,
    float* __restrict__ out)
{
    __shared__ float s_a[32 * 66];
    __shared__ float s_w[32][8];

    int tid = threadIdx.x;
    int tx  = tid & 7;
    int ty  = tid >> 3;
    int n0  = blockIdx.x * 8;

    float acc[4] = {0.f, 0.f, 0.f, 0.f};

    for (int k0 = 0; k0 < DM; k0 += 32) {
#pragma unroll
        for (int i = 0; i < 16; i++) {
            int idx = i * 128 + tid;
            int m   = idx >> 5;
            int kk  = idx & 31;
            s_a[kk * 66 + m] = g_hd[m * DM + k0 + kk];
        }
        {
            int kk = tid >> 2;
            int n2 = (tid & 3) * 2;
            const float* wp = Wd2 + (size_t)(k0 + kk) * SS + n0 + n2;
            s_w[kk][n2]     = wp[0];
            s_w[kk][n2 + 1] = wp[1];
        }
        __syncthreads();

#pragma unroll
        for (int kk = 0; kk < 32; kk++) {
            float w = s_w[kk][tx];
            const float* ap = &s_a[kk * 66 + ty * 4];
            float2 a01 = *(const float2*)ap;
            float2 a23 = *(const float2*)(ap + 2);
            acc[0] += a01.x * w;
            acc[1] += a01.y * w;
            acc[2] += a23.x * w;
            acc[3] += a23.y * w;
        }
        __syncthreads();
    }

    float* snext = g_sbuf[(t + 1) & 1];
    int n = n0 + tx;
    float bv = bd2[n];
#pragma unroll
    for (int im = 0; im < 4; im++) {
        int m = ty * 4 + im;
        float v = acc[im] + bv;
        snext[m * SS + n] = v;                          // feed next step
        out[(size_t)m * SS * TT + (size_t)n * TT + t] = v;  // [B,S,T]
    }
}

// ---------------------------------------------------------------------------
__global__ void zero_sbuf_kernel()
{
    int i = blockIdx.x * 256 + threadIdx.x;
    if (i < BATCH * SS) g_sbuf[0][i] = 0.f;
}

// ---------------------------------------------------------------------------
extern "C" void kernel_launch(void* const* d_in, const int* in_sizes, int n_in,
                              void* d_out, int out_size)
{
    const float* x   = (const float*)d_in[0];
    const float* We1 = (const float*)d_in[1];
    const float* be1 = (const float*)d_in[2];
    const float* We2 = (const float*)d_in[3];
    const float* be2 = (const float*)d_in[4];
    const float* Wd1 = (const float*)d_in[5];
    const float* bd1 = (const float*)d_in[6];
    const float* Wd2 = (const float*)d_in[7];
    const float* bd2 = (const float*)d_in[8];
    float* out = (float*)d_out;

    // encoder (parallel)
    transpose_x_kernel<<<dim3(TT / 32, SS / 32, BATCH), dim3(32, 8)>>>(x);
    enc_gemm_kernel<0><<<dim3((EM + 63) / 64, MROWS / 64), 256>>>(We1, be1);
    enc_gemm_kernel<1><<<dim3(1, MROWS / 64), 256>>>(We2, be2);

    // decoder (sequential recurrence)
    zero_sbuf_kernel<<<(BATCH * SS + 255) / 256, 256>>>();
    for (int t = 0; t < TT; t++) {
        dec_layer1_kernel<<<DM / 8, 128>>>(t, Wd1, bd1);
        dec_layer2_kernel<<<SS / 8, 128>>>(t, Wd2, bd2, out);
    }
}

// round 2
// speedup vs baseline: 2.1334x; 2.1334x over previous
#include <cuda_runtime.h>

// ---------------------------------------------------------------------------
// StepWiseMLPAutoEncoder
//   encoder: controls = (relu(comb @ We1 + be1)) @ We2 + be2   [fully parallel]
//   decoder: 256-step recurrence; per step two 512-thread kernels with
//            in-block 4-way K-split, warp-private double-buffered smem staging
// ---------------------------------------------------------------------------

#define BATCH 64
#define SS    1024      // stft buckets
#define TT    256       // sequence length
#define HH    64        // hidden
#define EM    1056      // encoder mid
#define DM    1056      // decoder mid
#define KC    2048      // 2*SS (comb width)
#define MROWS (BATCH*TT) // 16384

// scratch (device globals: no allocation allowed)
__device__ float g_xT[BATCH * TT * SS];          // x transposed to [B,T,S]
__device__ float g_h1[(size_t)MROWS * EM];       // encoder hidden
__device__ float g_ctrl[MROWS * HH];             // controls [B,T,H]
__device__ float g_hd[BATCH * DM];               // decoder hidden (per step)
__device__ float g_sbuf[2][BATCH * SS];          // ping-pong prev_stft

// ---------------------------------------------------------------------------
// x[b,s,t] -> xT[b,t,s]
// ---------------------------------------------------------------------------
__global__ void transpose_x_kernel(const float* __restrict__ x)
{
    __shared__ float tile[32][33];
    int b  = blockIdx.z;
    int t0 = blockIdx.x * 32;
    int s0 = blockIdx.y * 32;
    const float* xb  = x    + (size_t)b * SS * TT;
    float*       xTb = g_xT + (size_t)b * TT * SS;
    int tx = threadIdx.x, ty = threadIdx.y;
#pragma unroll
    for (int j = 0; j < 32; j += 8)
        tile[ty + j][tx] = xb[(s0 + ty + j) * TT + t0 + tx];
    __syncthreads();
#pragma unroll
    for (int j = 0; j < 32; j += 8)
        xTb[(t0 + ty + j) * SS + s0 + tx] = tile[tx][ty + j];
}

// ---------------------------------------------------------------------------
// Encoder GEMM, 64x64 tile, BK=16, 256 threads, 4x4 per thread. (unchanged)
// MODE 0: A = comb (gathered from g_xT), C = relu(A@We1+be1) -> g_h1
// MODE 1: A = g_h1,                      C = A@We2+be2       -> g_ctrl
// ---------------------------------------------------------------------------
template<int MODE>
__global__ __launch_bounds__(256) void enc_gemm_kernel(
    const float* __restrict__ Bmat, const float* __restrict__ bias)
{
    constexpr int N = (MODE == 0) ? EM : HH;
    constexpr int K = (MODE == 0) ? KC : EM;

    __shared__ float As[16][64];
    __shared__ float Bs[16][64];

    int tid  = threadIdx.x;
    int arow = tid >> 2;
    int acol = (tid & 3) * 4;
    int tn   = tid & 15;
    int tm   = tid >> 4;
    int n0   = blockIdx.x * 64;
    int r0   = blockIdx.y * 64;

    float acc[4][4] = {};

    int r = r0 + arow;
    const float* aprev = nullptr;
    const float* acur  = nullptr;
    if (MODE == 0) {
        int bb = r >> 8;
        int t  = r & 255;
        acur  = g_xT + ((size_t)((bb << 8) + t)) * SS;
        aprev = (t > 0) ? (acur - SS) : nullptr;
    } else {
        acur = g_h1 + (size_t)r * K;
    }

    for (int kc = 0; kc < K; kc += 16) {
        float4 av = make_float4(0.f, 0.f, 0.f, 0.f);
        int kg = kc + acol;
        if (MODE == 0) {
            if (kg < SS) {
                if (aprev) av = *(const float4*)(aprev + kg);
            } else {
                av = *(const float4*)(acur + kg - SS);
            }
        } else {
            av = *(const float4*)(acur + kg);
        }
        As[acol + 0][arow] = av.x;
        As[acol + 1][arow] = av.y;
        As[acol + 2][arow] = av.z;
        As[acol + 3][arow] = av.w;

#pragma unroll
        for (int it = 0; it < 4; it++) {
            int k = (tid >> 6) + it * 4;
            int n = tid & 63;
            int ng = n0 + n;
            float v = 0.f;
            if (ng < N) v = Bmat[(size_t)(kc + k) * N + ng];
            Bs[k][n] = v;
        }
        __syncthreads();

#pragma unroll
        for (int kk = 0; kk < 16; kk++) {
            float4 a4 = *(const float4*)&As[kk][tm * 4];
            float4 b4 = *(const float4*)&Bs[kk][tn * 4];
            float aa[4] = {a4.x, a4.y, a4.z, a4.w};
            float bb[4] = {b4.x, b4.y, b4.z, b4.w};
#pragma unroll
            for (int i = 0; i < 4; i++)
#pragma unroll
                for (int j = 0; j < 4; j++)
                    acc[i][j] += aa[i] * bb[j];
        }
        __syncthreads();
    }

#pragma unroll
    for (int j = 0; j < 4; j++) {
        int ng = n0 + tn * 4 + j;
        if (ng < N) {
            float bv = bias[ng];
#pragma unroll
            for (int i = 0; i < 4; i++) {
                int rr = r0 + tm * 4 + i;
                float v = acc[i][j] + bv;
                if (MODE == 0)
                    g_h1[(size_t)rr * EM + ng] = fmaxf(v, 0.f);
                else
                    g_ctrl[rr * HH + ng] = v;
            }
        }
    }
}

// ---------------------------------------------------------------------------
// Decoder step kernel. One launch computes one layer for one timestep.
//   MODE 0: g_hd[64,1056] = relu([ctrl_t | prev] @ Wd1 + bd1)   K=1088 N=1056
//   MODE 1: v = g_hd @ Wd2 + bd2 -> g_sbuf[(t+1)&1], d_out      K=1056 N=1024
// Block: 512 threads = 4 K-split groups x 4 warps. Each block owns 64m x 8n.
// Warp-private smem staging (double buffered), only __syncwarp in mainloop.
// Dynamic smem: 2 bufs * 16 warps * 512 floats + 2048 floats reduce = 73728 B.
// ---------------------------------------------------------------------------
#define DEC_CK   16
#define DEC_SMEM 73728

template<int MODE>
__global__ __launch_bounds__(512) void dec_step_kernel(
    int t, const float* __restrict__ W, const float* __restrict__ bias,
    float* __restrict__ gout)
{
    constexpr int NOUT = (MODE == 0) ? DM : SS;

    extern __shared__ float sm[];
    float* s_red = sm + 2 * 16 * 512;   // [64*8*4]

    int tid  = threadIdx.x;
    int warp = tid >> 5;
    int lane = tid & 31;
    int kz   = warp >> 2;          // 0..3 K-split group
    int wg   = warp & 3;           // m-group within block: m base = wg*16
    int tx   = lane & 7;           // n within tile
    int tyl  = lane >> 3;          // 0..3, each owns 4 m rows
    int n0   = blockIdx.x * 8;

    // K range for this group (all chunks full DEC_CK wide)
    int nch, kstart;
    if (MODE == 0) { nch = 17; kstart = kz * 272; }                    // 4*272=1088
    else { nch = (kz < 2) ? 17 : 16;                                    // 272*2+256*2=1056
           kstart = (kz < 2) ? kz * 272 : 544 + (kz - 2) * 256; }

    const float* sprev = g_sbuf[t & 1];

    // A loader: row m, col k (both MODEs, k multiple of 4)
    auto load_a = [&](int m, int k) -> float4 {
        if (MODE == 0) {
            if (k < HH) return *(const float4*)(g_ctrl + (m * TT + t) * HH + k);
            return *(const float4*)(sprev + m * SS + (k - HH));
        } else {
            return *(const float4*)(g_hd + m * DM + k);
        }
    };

    // per-lane staging slots
    int a_m0 = (lane >> 2);            // f4id = lane      -> m_local 0..7
    int a_c0 = (lane & 3) * 4;         //                 -> k offset in chunk
    int a_m1 = a_m0 + 8;               // f4id = lane + 32 -> m_local 8..15
    int w_kk = lane >> 1;              // 0..15
    int w_n4 = (lane & 1) * 4;         // 0 or 4

    auto load_chunk = [&](int c, float4& A0, float4& A1, float4& RW) {
        int kb = kstart + c * DEC_CK;
        A0 = load_a(wg * 16 + a_m0, kb + a_c0);
        A1 = load_a(wg * 16 + a_m1, kb + a_c0);
        RW = *(const float4*)(W + (size_t)(kb + w_kk) * NOUT + n0 + w_n4);
    };

    float acc[4] = {0.f, 0.f, 0.f, 0.f};
    float4 ra0, ra1, rw;
    load_chunk(0, ra0, ra1, rw);

    int buf = 0;
    for (int c = 0; c < nch; c++) {
        float* base = sm + (buf * 16 + warp) * 512;   // warp-private region
        // stage: a[16][20] at base, w[16][12] at base+320
        *(float4*)(base + a_m0 * 20 + a_c0) = ra0;
        *(float4*)(base + a_m1 * 20 + a_c0) = ra1;
        *(float4*)(base + 320 + w_kk * 12 + w_n4) = rw;
        __syncwarp();

        if (c + 1 < nch) load_chunk(c + 1, ra0, ra1, rw);

        const float* ab = base;
        const float* wb = base + 320;
#pragma unroll
        for (int q = 0; q < 4; q++) {
            float4 a4[4];
#pragma unroll
            for (int i = 0; i < 4; i++)
                a4[i] = *(const float4*)(ab + (tyl * 4 + i) * 20 + q * 4);
#pragma unroll
            for (int kk = 0; kk < 4; kk++) {
                float w = wb[(q * 4 + kk) * 12 + tx];
                acc[0] += ((const float*)&a4[0])[kk] * w;
                acc[1] += ((const float*)&a4[1])[kk] * w;
                acc[2] += ((const float*)&a4[2])[kk] * w;
                acc[3] += ((const float*)&a4[3])[kk] * w;
            }
        }
        __syncwarp();
        buf ^= 1;
    }

    // cross-group (K-split) reduction
#pragma unroll
    for (int i = 0; i < 4; i++) {
        int m = wg * 16 + tyl * 4 + i;
        s_red[(m * 8 + tx) * 4 + kz] = acc[i];
    }
    __syncthreads();

    if (kz == 0) {
        int n = n0 + tx;
        float bv = bias[n];
#pragma unroll
        for (int i = 0; i < 4; i++) {
            int m = wg * 16 + tyl * 4 + i;
            const float* p = &s_red[(m * 8 + tx) * 4];
            float v = p[0] + p[1] + p[2] + p[3] + bv;
            if (MODE == 0) {
                g_hd[m * DM + n] = fmaxf(v, 0.f);
            } else {
                g_sbuf[(t + 1) & 1][m * SS + n] = v;
                gout[((size_t)m * SS + n) * TT + t] = v;
            }
        }
    }
}

// ---------------------------------------------------------------------------
__global__ void zero_sbuf_kernel()
{
    int i = blockIdx.x * 256 + threadIdx.x;
    if (i < BATCH * SS) g_sbuf[0][i] = 0.f;
}

// ---------------------------------------------------------------------------
extern "C" void kernel_launch(void* const* d_in, const int* in_sizes, int n_in,
                              void* d_out, int out_size)
{
    const float* x   = (const float*)d_in[0];
    const float* We1 = (const float*)d_in[1];
    const float* be1 = (const float*)d_in[2];
    const float* We2 = (const float*)d_in[3];
    const float* be2 = (const float*)d_in[4];
    const float* Wd1 = (const float*)d_in[5];
    const float* bd1 = (const float*)d_in[6];
    const float* Wd2 = (const float*)d_in[7];
    const float* bd2 = (const float*)d_in[8];
    float* out = (float*)d_out;

    cudaFuncSetAttribute(dec_step_kernel<0>,
                         cudaFuncAttributeMaxDynamicSharedMemorySize, DEC_SMEM);
    cudaFuncSetAttribute(dec_step_kernel<1>,
                         cudaFuncAttributeMaxDynamicSharedMemorySize, DEC_SMEM);

    // encoder (parallel)
    transpose_x_kernel<<<dim3(TT / 32, SS / 32, BATCH), dim3(32, 8)>>>(x);
    enc_gemm_kernel<0><<<dim3((EM + 63) / 64, MROWS / 64), 256>>>(We1, be1);
    enc_gemm_kernel<1><<<dim3(1, MROWS / 64), 256>>>(We2, be2);

    // decoder (sequential recurrence)
    zero_sbuf_kernel<<<(BATCH * SS + 255) / 256, 256>>>();
    for (int t = 0; t < TT; t++) {
        dec_step_kernel<0><<<DM / 8, 512, DEC_SMEM>>>(t, Wd1, bd1, nullptr);
        dec_step_kernel<1><<<SS / 8, 512, DEC_SMEM>>>(t, Wd2, bd2, out);
    }
}

// round 3
// speedup vs baseline: 2.1511x; 1.0083x over previous
#include <cuda_runtime.h>

// ---------------------------------------------------------------------------
// StepWiseMLPAutoEncoder
//   encoder: controls = (relu(comb @ We1 + be1)) @ We2 + be2   [parallel GEMMs]
//   decoder: ONE persistent kernel, 256 recurrent steps, grid barrier between
//            layers; weights cached (transposed) in SMEM for all steps.
// ---------------------------------------------------------------------------

#define BATCH 64
#define SS    1024      // stft buckets
#define TT    256       // sequence length
#define HH    64        // hidden
#define EM    1056      // encoder mid
#define DM    1056      // decoder mid
#define KC    2048      // 2*SS (comb width)
#define KD1   1088      // SS + HH
#define MROWS (BATCH*TT)
#define NBLK  132       // decoder blocks (1056/8); all co-resident (< 148 SMs)

// scratch (device globals: no allocation allowed)
__device__ float g_xT[BATCH * TT * SS];            // x transposed [B,T,S]
__device__ float g_h1[(size_t)MROWS * EM];         // encoder hidden
__device__ float g_ctrlT[TT * HH * BATCH];         // controls [T,H,B] (k-major)
__device__ float g_hdT[DM * BATCH];                // decoder hidden [K,B]
__device__ float g_sbufT[2][SS * BATCH];           // prev_stft ping-pong [S,B]
__device__ unsigned g_bar = 0;                     // grid barrier state
__device__ unsigned g_gen = 0;

// ---------------------------------------------------------------------------
__device__ __forceinline__ void grid_sync(int nb)
{
    __threadfence();
    __syncthreads();
    if (threadIdx.x == 0) {
        volatile unsigned* vgen = &g_gen;
        unsigned my = *vgen;
        if (atomicAdd(&g_bar, 1u) == (unsigned)(nb - 1)) {
            atomicExch(&g_bar, 0u);
            __threadfence();
            atomicExch(&g_gen, my + 1u);
        } else {
            while (*vgen == my) { }
            __threadfence();
        }
    }
    __syncthreads();
}

// ---------------------------------------------------------------------------
// x[b,s,t] -> xT[b,t,s]
// ---------------------------------------------------------------------------
__global__ void transpose_x_kernel(const float* __restrict__ x)
{
    __shared__ float tile[32][33];
    int b  = blockIdx.z;
    int t0 = blockIdx.x * 32;
    int s0 = blockIdx.y * 32;
    const float* xb  = x    + (size_t)b * SS * TT;
    float*       xTb = g_xT + (size_t)b * TT * SS;
    int tx = threadIdx.x, ty = threadIdx.y;
#pragma unroll
    for (int j = 0; j < 32; j += 8)
        tile[ty + j][tx] = xb[(s0 + ty + j) * TT + t0 + tx];
    __syncthreads();
#pragma unroll
    for (int j = 0; j < 32; j += 8)
        xTb[(t0 + ty + j) * SS + s0 + tx] = tile[tx][ty + j];
}

// ---------------------------------------------------------------------------
// Encoder GEMM, 64x64 tile, BK=16, 256 threads, 4x4 per thread.
// MODE 0: A = comb (gathered from g_xT), C = relu(A@We1+be1) -> g_h1
// MODE 1: A = g_h1,                      C = A@We2+be2       -> g_ctrlT
// ---------------------------------------------------------------------------
template<int MODE>
__global__ __launch_bounds__(256) void enc_gemm_kernel(
    const float* __restrict__ Bmat, const float* __restrict__ bias)
{
    constexpr int N = (MODE == 0) ? EM : HH;
    constexpr int K = (MODE == 0) ? KC : EM;

    __shared__ float As[16][64];
    __shared__ float Bs[16][64];

    int tid  = threadIdx.x;
    int arow = tid >> 2;
    int acol = (tid & 3) * 4;
    int tn   = tid & 15;
    int tm   = tid >> 4;
    int n0   = blockIdx.x * 64;
    int r0   = blockIdx.y * 64;

    float acc[4][4] = {};

    int r = r0 + arow;
    const float* aprev = nullptr;
    const float* acur  = nullptr;
    if (MODE == 0) {
        int bb = r >> 8;
        int t  = r & 255;
        acur  = g_xT + ((size_t)((bb << 8) + t)) * SS;
        aprev = (t > 0) ? (acur - SS) : nullptr;
    } else {
        acur = g_h1 + (size_t)r * K;
    }

    for (int kc = 0; kc < K; kc += 16) {
        float4 av = make_float4(0.f, 0.f, 0.f, 0.f);
        int kg = kc + acol;
        if (MODE == 0) {
            if (kg < SS) {
                if (aprev) av = *(const float4*)(aprev + kg);
            } else {
                av = *(const float4*)(acur + kg - SS);
            }
        } else {
            av = *(const float4*)(acur + kg);
        }
        As[acol + 0][arow] = av.x;
        As[acol + 1][arow] = av.y;
        As[acol + 2][arow] = av.z;
        As[acol + 3][arow] = av.w;

#pragma unroll
        for (int it = 0; it < 4; it++) {
            int k = (tid >> 6) + it * 4;
            int n = tid & 63;
            int ng = n0 + n;
            float v = 0.f;
            if (ng < N) v = Bmat[(size_t)(kc + k) * N + ng];
            Bs[k][n] = v;
        }
        __syncthreads();

#pragma unroll
        for (int kk = 0; kk < 16; kk++) {
            float4 a4 = *(const float4*)&As[kk][tm * 4];
            float4 b4 = *(const float4*)&Bs[kk][tn * 4];
            float aa[4] = {a4.x, a4.y, a4.z, a4.w};
            float bb[4] = {b4.x, b4.y, b4.z, b4.w};
#pragma unroll
            for (int i = 0; i < 4; i++)
#pragma unroll
                for (int j = 0; j < 4; j++)
                    acc[i][j] += aa[i] * bb[j];
        }
        __syncthreads();
    }

#pragma unroll
    for (int j = 0; j < 4; j++) {
        int ng = n0 + tn * 4 + j;
        if (ng < N) {
            float bv = bias[ng];
#pragma unroll
            for (int i = 0; i < 4; i++) {
                int rr = r0 + tm * 4 + i;
                float v = acc[i][j] + bv;
                if (MODE == 0) {
                    g_h1[(size_t)rr * EM + ng] = fmaxf(v, 0.f);
                } else {
                    int bb = rr >> 8;          // rr = b*TT + t
                    int tt = rr & 255;
                    g_ctrlT[(tt * HH + ng) * BATCH + bb] = v;
                }
            }
        }
    }
}

// ---------------------------------------------------------------------------
// Persistent decoder: 132 blocks x 512 threads. Block owns 8 output columns
// of each layer (blocks >=128 idle in layer2). 16 warps = 2 m-halves x 8
// k-split groups; each thread: 1 m, 8 n accumulators.
// SMEM: Ws1[8][1088] + Ws2[8][1056] transposed weight slices (persist all
// steps) + red[8g][8n][64m] reduction buffer = 84992 B dynamic.
// ---------------------------------------------------------------------------
#define DEC_SMEM ((8*1088 + 8*1056 + 8*8*64) * 4)

__global__ __launch_bounds__(512) void dec_persistent_kernel(
    const float* __restrict__ Wd1, const float* __restrict__ bd1,
    const float* __restrict__ Wd2, const float* __restrict__ bd2,
    float* __restrict__ out)
{
    extern __shared__ float sm[];
    float* Ws1 = sm;                       // [8][1088]
    float* Ws2 = sm + 8 * 1088;            // [8][1056]
    float* red = sm + 8 * 1088 + 8 * 1056; // [8][8][64]

    int tid = threadIdx.x;
    int bid = blockIdx.x;
    int n0  = bid * 8;

    // one-time: cache transposed weight slices in SMEM
    for (int i = tid; i < 8 * KD1; i += 512) {
        int k = i >> 3, n = i & 7;
        Ws1[n * KD1 + k] = Wd1[(size_t)k * DM + n0 + n];
    }
    if (bid < 128) {
        for (int i = tid; i < 8 * DM; i += 512) {
            int k = i >> 3, n = i & 7;
            Ws2[n * DM + k] = Wd2[(size_t)k * SS + n0 + n];
        }
    }
    // zero initial prev_stft
    {
        int i = bid * 512 + tid;
        if (i < SS * BATCH) g_sbufT[0][i] = 0.f;
    }

    int warp = tid >> 5, lane = tid & 31;
    int g = warp >> 1;                    // k-split group 0..7
    int m = ((warp & 1) << 5) + lane;     // batch row 0..63
    int en = tid >> 6;                    // epilogue n 0..7
    int em = tid & 63;                    // epilogue m 0..63

    float bv1 = bd1[n0 + en];
    float bv2 = (bid < 128) ? bd2[n0 + en] : 0.f;

    grid_sync(NBLK);

    for (int t = 0; t < TT; t++) {
        const float* sbT = g_sbufT[t & 1];
        const float* ctrl_base = g_ctrlT + t * HH * BATCH;

        // ---------- layer 1: g_hdT = relu([ctrl_t | prev] @ Wd1 + bd1)
        {
            float acc[8] = {};
            int kb = g * 136;             // 8 * 136 = 1088
            const float* s0 = (kb < HH) ? (ctrl_base + kb * 64)
                                        : (sbT + (kb - HH) * 64);
            float a0 = s0[m], a1 = s0[64 + m], a2 = s0[128 + m], a3 = s0[192 + m];

            for (int k = kb; k < kb + 136; k += 4) {
                float b0 = 0.f, b1 = 0.f, b2 = 0.f, b3 = 0.f;
                if (k + 4 < kb + 136) {
                    int kn = k + 4;
                    const float* s1 = (kn < HH) ? (ctrl_base + kn * 64)
                                                : (sbT + (kn - HH) * 64);
                    b0 = s1[m]; b1 = s1[64 + m]; b2 = s1[128 + m]; b3 = s1[192 + m];
                }
                const float* w = Ws1 + k;
#pragma unroll
                for (int n = 0; n < 8; n++) {
                    float4 w4 = *(const float4*)(w + n * KD1);
                    acc[n] += a0 * w4.x + a1 * w4.y + a2 * w4.z + a3 * w4.w;
                }
                a0 = b0; a1 = b1; a2 = b2; a3 = b3;
            }
#pragma unroll
            for (int n = 0; n < 8; n++)
                red[(g * 8 + n) * 64 + m] = acc[n];
            __syncthreads();

            float v = 0.f;
#pragma unroll
            for (int gg = 0; gg < 8; gg++)
                v += red[(gg * 8 + en) * 64 + em];
            v += bv1;
            g_hdT[(n0 + en) * 64 + em] = fmaxf(v, 0.f);
        }
        grid_sync(NBLK);

        // ---------- layer 2: out_t = g_hd @ Wd2 + bd2
        if (bid < 128) {
            float acc[8] = {};
            int kb = g * 132;             // 8 * 132 = 1056
            const float* s0 = g_hdT + kb * 64;
            float a0 = s0[m], a1 = s0[64 + m], a2 = s0[128 + m], a3 = s0[192 + m];

            for (int k = kb; k < kb + 132; k += 4) {
                float b0 = 0.f, b1 = 0.f, b2 = 0.f, b3 = 0.f;
                if (k + 4 < kb + 132) {
                    const float* s1 = g_hdT + (k + 4) * 64;
                    b0 = s1[m]; b1 = s1[64 + m]; b2 = s1[128 + m]; b3 = s1[192 + m];
                }
                const float* w = Ws2 + k;
#pragma unroll
                for (int n = 0; n < 8; n++) {
                    float4 w4 = *(const float4*)(w + n * DM);
                    acc[n] += a0 * w4.x + a1 * w4.y + a2 * w4.z + a3 * w4.w;
                }
                a0 = b0; a1 = b1; a2 = b2; a3 = b3;
            }
#pragma unroll
            for (int n = 0; n < 8; n++)
                red[(g * 8 + n) * 64 + m] = acc[n];
            __syncthreads();

            float v = 0.f;
#pragma unroll
            for (int gg = 0; gg < 8; gg++)
                v += red[(gg * 8 + en) * 64 + em];
            v += bv2;
            int s = n0 + en;
            g_sbufT[(t + 1) & 1][s * 64 + em] = v;
            out[((size_t)em * SS + s) * TT + t] = v;
        }
        grid_sync(NBLK);
    }
}

// ---------------------------------------------------------------------------
extern "C" void kernel_launch(void* const* d_in, const int* in_sizes, int n_in,
                              void* d_out, int out_size)
{
    const float* x   = (const float*)d_in[0];
    const float* We1 = (const float*)d_in[1];
    const float* be1 = (const float*)d_in[2];
    const float* We2 = (const float*)d_in[3];
    const float* be2 = (const float*)d_in[4];
    const float* Wd1 = (const float*)d_in[5];
    const float* bd1 = (const float*)d_in[6];
    const float* Wd2 = (const float*)d_in[7];
    const float* bd2 = (const float*)d_in[8];
    float* out = (float*)d_out;

    cudaFuncSetAttribute(dec_persistent_kernel,
                         cudaFuncAttributeMaxDynamicSharedMemorySize, DEC_SMEM);

    // encoder (parallel)
    transpose_x_kernel<<<dim3(TT / 32, SS / 32, BATCH), dim3(32, 8)>>>(x);
    enc_gemm_kernel<0><<<dim3((EM + 63) / 64, MROWS / 64), 256>>>(We1, be1);
    enc_gemm_kernel<1><<<dim3(1, MROWS / 64), 256>>>(We2, be2);

    // decoder: single persistent kernel over all 256 steps
    dec_persistent_kernel<<<NBLK, 512, DEC_SMEM>>>(Wd1, bd1, Wd2, bd2, out);
}

// round 4
// speedup vs baseline: 2.5737x; 1.1964x over previous
#include <cuda_runtime.h>

// ---------------------------------------------------------------------------
// StepWiseMLPAutoEncoder — fp32 with packed fma.rn.f32x2 (2x fp32 throughput)
// ---------------------------------------------------------------------------

#define BATCH 64
#define SS    1024
#define TT    256
#define HH    64
#define EM    1056
#define DM    1056
#define KC    2048
#define KD1   1088
#define MROWS (BATCH*TT)
#define NBLK  132

typedef unsigned long long u64;

// scratch (device globals: no allocation allowed)  — padded for prefetch overshoot
__device__ float g_xT[BATCH * TT * SS];
__device__ float g_h1[(size_t)MROWS * EM];
__device__ float g_ctrlT[TT * HH * BATCH + 256];     // [T,H,B] k-major
__device__ float g_hdT[DM * BATCH + 256];            // [K,B]
__device__ float g_sbufT[2][SS * BATCH + 256];       // [S,B] ping-pong
__device__ unsigned g_bar = 0;
__device__ unsigned g_gen = 0;

// ---- packed fp32x2 helpers -------------------------------------------------
__device__ __forceinline__ u64 pk2(float lo, float hi) {
    u64 r; asm("mov.b64 %0, {%1, %2};" : "=l"(r) : "f"(lo), "f"(hi)); return r;
}
__device__ __forceinline__ void fma2(u64& d, u64 a, u64 b) {
    asm("fma.rn.f32x2 %0, %1, %2, %0;" : "+l"(d) : "l"(a), "l"(b));
}
__device__ __forceinline__ void unpk2(u64 v, float& lo, float& hi) {
    asm("mov.b64 {%0, %1}, %2;" : "=f"(lo), "=f"(hi) : "l"(v));
}

// ---------------------------------------------------------------------------
__device__ __forceinline__ void grid_sync(int nb)
{
    __threadfence();
    __syncthreads();
    if (threadIdx.x == 0) {
        volatile unsigned* vgen = &g_gen;
        unsigned my = *vgen;
        if (atomicAdd(&g_bar, 1u) == (unsigned)(nb - 1)) {
            atomicExch(&g_bar, 0u);
            __threadfence();
            atomicExch(&g_gen, my + 1u);
        } else {
            while (*vgen == my) { }
            __threadfence();
        }
    }
    __syncthreads();
}

// ---------------------------------------------------------------------------
// x[b,s,t] -> xT[b,t,s]
// ---------------------------------------------------------------------------
__global__ void transpose_x_kernel(const float* __restrict__ x)
{
    __shared__ float tile[32][33];
    int b  = blockIdx.z;
    int t0 = blockIdx.x * 32;
    int s0 = blockIdx.y * 32;
    const float* xb  = x    + (size_t)b * SS * TT;
    float*       xTb = g_xT + (size_t)b * TT * SS;
    int tx = threadIdx.x, ty = threadIdx.y;
#pragma unroll
    for (int j = 0; j < 32; j += 8)
        tile[ty + j][tx] = xb[(s0 + ty + j) * TT + t0 + tx];
    __syncthreads();
#pragma unroll
    for (int j = 0; j < 32; j += 8)
        xTb[(t0 + ty + j) * SS + s0 + tx] = tile[tx][ty + j];
}

// ---------------------------------------------------------------------------
// Encoder GEMM, 64x64 tile, BK=16, 256 threads, 4m x 4n per thread, f32x2.
// MODE 0: A = comb (from g_xT), C = relu(A@We1+be1) -> g_h1
// MODE 1: A = g_h1,             C = A@We2+be2       -> g_ctrlT
// ---------------------------------------------------------------------------
template<int MODE>
__global__ __launch_bounds__(256) void enc_gemm_kernel(
    const float* __restrict__ Bmat, const float* __restrict__ bias)
{
    constexpr int N = (MODE == 0) ? EM : HH;
    constexpr int K = (MODE == 0) ? KC : EM;

    __shared__ float As[16][64];
    __shared__ float Bs[16][64];

    int tid  = threadIdx.x;
    int arow = tid >> 2;
    int acol = (tid & 3) * 4;
    int tn   = tid & 15;
    int tm   = tid >> 4;
    int n0   = blockIdx.x * 64;
    int r0   = blockIdx.y * 64;

    u64 acc2[4][2];
#pragma unroll
    for (int i = 0; i < 4; i++) { acc2[i][0] = 0ULL; acc2[i][1] = 0ULL; }

    int r = r0 + arow;
    const float* aprev = nullptr;
    const float* acur  = nullptr;
    if (MODE == 0) {
        int bb = r >> 8;
        int t  = r & 255;
        acur  = g_xT + ((size_t)((bb << 8) + t)) * SS;
        aprev = (t > 0) ? (acur - SS) : nullptr;
    } else {
        acur = g_h1 + (size_t)r * K;
    }

    for (int kc = 0; kc < K; kc += 16) {
        float4 av = make_float4(0.f, 0.f, 0.f, 0.f);
        int kg = kc + acol;
        if (MODE == 0) {
            if (kg < SS) {
                if (aprev) av = *(const float4*)(aprev + kg);
            } else {
                av = *(const float4*)(acur + kg - SS);
            }
        } else {
            av = *(const float4*)(acur + kg);
        }
        As[acol + 0][arow] = av.x;
        As[acol + 1][arow] = av.y;
        As[acol + 2][arow] = av.z;
        As[acol + 3][arow] = av.w;

#pragma unroll
        for (int it = 0; it < 4; it++) {
            int k = (tid >> 6) + it * 4;
            int n = tid & 63;
            int ng = n0 + n;
            float v = 0.f;
            if (ng < N) v = Bmat[(size_t)(kc + k) * N + ng];
            Bs[k][n] = v;
        }
        __syncthreads();

#pragma unroll
        for (int kk = 0; kk < 16; kk++) {
            float4 a4 = *(const float4*)&As[kk][tm * 4];
            ulonglong2 b2 = *(const ulonglong2*)&Bs[kk][tn * 4];
            u64 d0 = pk2(a4.x, a4.x);
            u64 d1 = pk2(a4.y, a4.y);
            u64 d2 = pk2(a4.z, a4.z);
            u64 d3 = pk2(a4.w, a4.w);
            fma2(acc2[0][0], d0, b2.x); fma2(acc2[0][1], d0, b2.y);
            fma2(acc2[1][0], d1, b2.x); fma2(acc2[1][1], d1, b2.y);
            fma2(acc2[2][0], d2, b2.x); fma2(acc2[2][1], d2, b2.y);
            fma2(acc2[3][0], d3, b2.x); fma2(acc2[3][1], d3, b2.y);
        }
        __syncthreads();
    }

#pragma unroll
    for (int i = 0; i < 4; i++) {
        float c[4];
        unpk2(acc2[i][0], c[0], c[1]);
        unpk2(acc2[i][1], c[2], c[3]);
        int rr = r0 + tm * 4 + i;
#pragma unroll
        for (int j = 0; j < 4; j++) {
            int ng = n0 + tn * 4 + j;
            if (ng < N) {
                float v = c[j] + bias[ng];
                if (MODE == 0) {
                    g_h1[(size_t)rr * EM + ng] = fmaxf(v, 0.f);
                } else {
                    int bb = rr >> 8;
                    int tt = rr & 255;
                    g_ctrlT[(tt * HH + ng) * BATCH + bb] = v;
                }
            }
        }
    }
}

// ---------------------------------------------------------------------------
// Persistent decoder: 132 blocks x 512 threads; block owns 8 output columns.
// 16 warps = 8 k-split groups x 2 m-halves. Thread: 1 m-row, 8 n (4 f32x2
// pairs). Weights cached in SMEM k-row-major [k][8] for packed LDS.128.
// ---------------------------------------------------------------------------
#define DEC_SMEM ((KD1*8 + DM*8 + 8*8*64) * 4)

// inner GEMM segment: acc over nk rows starting at activation ptr src
// (stride 64 per k) with weight rows wp = Ws + k0*8
__device__ __forceinline__ void dec_seg(
    u64 acc[4], const float* __restrict__ src, const float* __restrict__ Ws,
    int k0, int nk, int m)
{
    const float* s = src + m;
    const u64* wp = (const u64*)(Ws + k0 * 8);
    float av[4];
#pragma unroll
    for (int kk = 0; kk < 4; kk++) av[kk] = s[64 * kk];

    for (int i = 0; i < nk; i += 4) {
        s += 256;
        float nv[4];
#pragma unroll
        for (int kk = 0; kk < 4; kk++) nv[kk] = s[64 * kk];  // prefetch (padded)
#pragma unroll
        for (int kk = 0; kk < 4; kk++) {
            u64 ad = pk2(av[kk], av[kk]);
            ulonglong2 w01 = *(const ulonglong2*)(wp);
            ulonglong2 w23 = *(const ulonglong2*)(wp + 2);
            wp += 4;
            fma2(acc[0], ad, w01.x);
            fma2(acc[1], ad, w01.y);
            fma2(acc[2], ad, w23.x);
            fma2(acc[3], ad, w23.y);
        }
#pragma unroll
        for (int kk = 0; kk < 4; kk++) av[kk] = nv[kk];
    }
}

__global__ __launch_bounds__(512) void dec_persistent_kernel(
    const float* __restrict__ Wd1, const float* __restrict__ bd1,
    const float* __restrict__ Wd2, const float* __restrict__ bd2,
    float* __restrict__ out)
{
    extern __shared__ float sm[];
    float* Ws1 = sm;                       // [KD1][8]
    float* Ws2 = sm + KD1 * 8;             // [DM][8]
    float* red = sm + KD1 * 8 + DM * 8;    // [8g][8n][64m]

    int tid = threadIdx.x;
    int bid = blockIdx.x;
    int n0  = bid * 8;

    // one-time: cache weight slices k-row-major
    for (int i = tid; i < 8 * KD1; i += 512) {
        int k = i >> 3, n = i & 7;
        Ws1[i] = Wd1[(size_t)k * DM + n0 + n];
    }
    if (bid < 128) {
        for (int i = tid; i < 8 * DM; i += 512) {
            int k = i >> 3, n = i & 7;
            Ws2[i] = Wd2[(size_t)k * SS + n0 + n];
        }
    }
    {
        int i = bid * 512 + tid;
        if (i < SS * BATCH) g_sbufT[0][i] = 0.f;
        if (i < 256) { g_sbufT[0][SS * BATCH + i] = 0.f; g_sbufT[1][SS * BATCH + i] = 0.f; }
    }

    int warp = tid >> 5, lane = tid & 31;
    int g = warp >> 1;
    int m = ((warp & 1) << 5) + lane;
    int en = tid >> 6;
    int em = tid & 63;

    float bv1 = bd1[n0 + en];
    float bv2 = (bid < 128) ? bd2[n0 + en] : 0.f;

    grid_sync(NBLK);

    for (int t = 0; t < TT; t++) {
        const float* sbT = g_sbufT[t & 1];
        const float* ctrl_base = g_ctrlT + t * HH * BATCH;

        // ---- layer 1: g_hdT = relu([ctrl_t | prev] @ Wd1 + bd1), K=1088
        {
            u64 acc[4] = {0ULL, 0ULL, 0ULL, 0ULL};
            if (g == 0) {
                dec_seg(acc, ctrl_base, Ws1, 0, HH, m);          // k 0..63
                dec_seg(acc, sbT, Ws1, HH, 136 - HH, m);         // k 64..135
            } else {
                int kb = g * 136;
                dec_seg(acc, sbT + (kb - HH) * 64, Ws1, kb, 136, m);
            }
#pragma unroll
            for (int p = 0; p < 4; p++) {
                float lo, hi; unpk2(acc[p], lo, hi);
                red[(g * 8 + 2 * p) * 64 + m]     = lo;
                red[(g * 8 + 2 * p + 1) * 64 + m] = hi;
            }
            __syncthreads();

            float v = bv1;
#pragma unroll
            for (int gg = 0; gg < 8; gg++)
                v += red[(gg * 8 + en) * 64 + em];
            g_hdT[(n0 + en) * 64 + em] = fmaxf(v, 0.f);
        }
        grid_sync(NBLK);

        // ---- layer 2: out_t = g_hd @ Wd2 + bd2, K=1056
        if (bid < 128) {
            u64 acc[4] = {0ULL, 0ULL, 0ULL, 0ULL};
            int kb = g * 132;
            dec_seg(acc, g_hdT + kb * 64, Ws2, kb, 132, m);
#pragma unroll
            for (int p = 0; p < 4; p++) {
                float lo, hi; unpk2(acc[p], lo, hi);
                red[(g * 8 + 2 * p) * 64 + m]     = lo;
                red[(g * 8 + 2 * p + 1) * 64 + m] = hi;
            }
            __syncthreads();

            float v = bv2;
#pragma unroll
            for (int gg = 0; gg < 8; gg++)
                v += red[(gg * 8 + en) * 64 + em];
            int s = n0 + en;
            g_sbufT[(t + 1) & 1][s * 64 + em] = v;
            out[((size_t)em * SS + s) * TT + t] = v;
        }
        grid_sync(NBLK);
    }
}

// ---------------------------------------------------------------------------
extern "C" void kernel_launch(void* const* d_in, const int* in_sizes, int n_in,
                              void* d_out, int out_size)
{
    const float* x   = (const float*)d_in[0];
    const float* We1 = (const float*)d_in[1];
    const float* be1 = (const float*)d_in[2];
    const float* We2 = (const float*)d_in[3];
    const float* be2 = (const float*)d_in[4];
    const float* Wd1 = (const float*)d_in[5];
    const float* bd1 = (const float*)d_in[6];
    const float* Wd2 = (const float*)d_in[7];
    const float* bd2 = (const float*)d_in[8];
    float* out = (float*)d_out;

    cudaFuncSetAttribute(dec_persistent_kernel,
                         cudaFuncAttributeMaxDynamicSharedMemorySize, DEC_SMEM);

    transpose_x_kernel<<<dim3(TT / 32, SS / 32, BATCH), dim3(32, 8)>>>(x);
    enc_gemm_kernel<0><<<dim3((EM + 63) / 64, MROWS / 64), 256>>>(We1, be1);
    enc_gemm_kernel<1><<<dim3(1, MROWS / 64), 256>>>(We2, be2);

    dec_persistent_kernel<<<NBLK, 512, DEC_SMEM>>>(Wd1, bd1, Wd2, bd2, out);
}

// round 5
// speedup vs baseline: 3.5221x; 1.3685x over previous
#include <cuda_runtime.h>

// ---------------------------------------------------------------------------
// StepWiseMLPAutoEncoder — fp32 with packed fma.rn.f32x2
// decoder: persistent kernel, 16-wide n-tiles, 16-way k-split, 1 warp/group
// ---------------------------------------------------------------------------

#define BATCH 64
#define SS    1024
#define TT    256
#define HH    64
#define EM    1056
#define DM    1056
#define KC    2048
#define KD1   1088
#define MROWS (BATCH*TT)
#define NBLK  132

typedef unsigned long long u64;

// scratch (device globals) — padded +256 floats for prefetch overshoot
__device__ float g_xT[BATCH * TT * SS];
__device__ float g_h1[(size_t)MROWS * EM];
__device__ float g_ctrlT[TT * HH * BATCH + 256];     // [T,H,B] k-major
__device__ float g_hdT[DM * BATCH + 256];            // [K,B]
__device__ float g_sbufT[2][SS * BATCH + 256];       // [S,B] ping-pong
__device__ unsigned g_bar = 0;
__device__ unsigned g_gen = 0;

// ---- packed fp32x2 helpers -------------------------------------------------
__device__ __forceinline__ u64 pk2(float lo, float hi) {
    u64 r; asm("mov.b64 %0, {%1, %2};" : "=l"(r) : "f"(lo), "f"(hi)); return r;
}
__device__ __forceinline__ void fma2(u64& d, u64 a, u64 b) {
    asm("fma.rn.f32x2 %0, %1, %2, %0;" : "+l"(d) : "l"(a), "l"(b));
}
__device__ __forceinline__ void unpk2(u64 v, float& lo, float& hi) {
    asm("mov.b64 {%0, %1}, %2;" : "=f"(lo), "=f"(hi) : "l"(v));
}

// ---------------------------------------------------------------------------
__device__ __forceinline__ void grid_sync(int nb)
{
    __threadfence();
    __syncthreads();
    if (threadIdx.x == 0) {
        volatile unsigned* vgen = &g_gen;
        unsigned my = *vgen;
        if (atomicAdd(&g_bar, 1u) == (unsigned)(nb - 1)) {
            atomicExch(&g_bar, 0u);
            __threadfence();
            atomicExch(&g_gen, my + 1u);
        } else {
            while (*vgen == my) { }
            __threadfence();
        }
    }
    __syncthreads();
}

// ---------------------------------------------------------------------------
// x[b,s,t] -> xT[b,t,s]
// ---------------------------------------------------------------------------
__global__ void transpose_x_kernel(const float* __restrict__ x)
{
    __shared__ float tile[32][33];
    int b  = blockIdx.z;
    int t0 = blockIdx.x * 32;
    int s0 = blockIdx.y * 32;
    const float* xb  = x    + (size_t)b * SS * TT;
    float*       xTb = g_xT + (size_t)b * TT * SS;
    int tx = threadIdx.x, ty = threadIdx.y;
#pragma unroll
    for (int j = 0; j < 32; j += 8)
        tile[ty + j][tx] = xb[(s0 + ty + j) * TT + t0 + tx];
    __syncthreads();
#pragma unroll
    for (int j = 0; j < 32; j += 8)
        xTb[(t0 + ty + j) * SS + s0 + tx] = tile[tx][ty + j];
}

// ---------------------------------------------------------------------------
// Encoder GEMM, 64x64 tile, BK=16, 256 threads, 4m x 4n per thread, f32x2.
// ---------------------------------------------------------------------------
template<int MODE>
__global__ __launch_bounds__(256) void enc_gemm_kernel(
    const float* __restrict__ Bmat, const float* __restrict__ bias)
{
    constexpr int N = (MODE == 0) ? EM : HH;
    constexpr int K = (MODE == 0) ? KC : EM;

    __shared__ float As[16][64];
    __shared__ float Bs[16][64];

    int tid  = threadIdx.x;
    int arow = tid >> 2;
    int acol = (tid & 3) * 4;
    int tn   = tid & 15;
    int tm   = tid >> 4;
    int n0   = blockIdx.x * 64;
    int r0   = blockIdx.y * 64;

    u64 acc2[4][2];
#pragma unroll
    for (int i = 0; i < 4; i++) { acc2[i][0] = 0ULL; acc2[i][1] = 0ULL; }

    int r = r0 + arow;
    const float* aprev = nullptr;
    const float* acur  = nullptr;
    if (MODE == 0) {
        int bb = r >> 8;
        int t  = r & 255;
        acur  = g_xT + ((size_t)((bb << 8) + t)) * SS;
        aprev = (t > 0) ? (acur - SS) : nullptr;
    } else {
        acur = g_h1 + (size_t)r * K;
    }

    for (int kc = 0; kc < K; kc += 16) {
        float4 av = make_float4(0.f, 0.f, 0.f, 0.f);
        int kg = kc + acol;
        if (MODE == 0) {
            if (kg < SS) {
                if (aprev) av = *(const float4*)(aprev + kg);
            } else {
                av = *(const float4*)(acur + kg - SS);
            }
        } else {
            av = *(const float4*)(acur + kg);
        }
        As[acol + 0][arow] = av.x;
        As[acol + 1][arow] = av.y;
        As[acol + 2][arow] = av.z;
        As[acol + 3][arow] = av.w;

#pragma unroll
        for (int it = 0; it < 4; it++) {
            int k = (tid >> 6) + it * 4;
            int n = tid & 63;
            int ng = n0 + n;
            float v = 0.f;
            if (ng < N) v = Bmat[(size_t)(kc + k) * N + ng];
            Bs[k][n] = v;
        }
        __syncthreads();

#pragma unroll
        for (int kk = 0; kk < 16; kk++) {
            float4 a4 = *(const float4*)&As[kk][tm * 4];
            ulonglong2 b2 = *(const ulonglong2*)&Bs[kk][tn * 4];
            u64 d0 = pk2(a4.x, a4.x);
            u64 d1 = pk2(a4.y, a4.y);
            u64 d2 = pk2(a4.z, a4.z);
            u64 d3 = pk2(a4.w, a4.w);
            fma2(acc2[0][0], d0, b2.x); fma2(acc2[0][1], d0, b2.y);
            fma2(acc2[1][0], d1, b2.x); fma2(acc2[1][1], d1, b2.y);
            fma2(acc2[2][0], d2, b2.x); fma2(acc2[2][1], d2, b2.y);
            fma2(acc2[3][0], d3, b2.x); fma2(acc2[3][1], d3, b2.y);
        }
        __syncthreads();
    }

#pragma unroll
    for (int i = 0; i < 4; i++) {
        float c[4];
        unpk2(acc2[i][0], c[0], c[1]);
        unpk2(acc2[i][1], c[2], c[3]);
        int rr = r0 + tm * 4 + i;
#pragma unroll
        for (int j = 0; j < 4; j++) {
            int ng = n0 + tn * 4 + j;
            if (ng < N) {
                float v = c[j] + bias[ng];
                if (MODE == 0) {
                    g_h1[(size_t)rr * EM + ng] = fmaxf(v, 0.f);
                } else {
                    int bb = rr >> 8;
                    int tt = rr & 255;
                    g_ctrlT[(tt * HH + ng) * BATCH + bb] = v;
                }
            }
        }
    }
}

// ---------------------------------------------------------------------------
// Persistent decoder.
// 132 blocks x 512 thr. Block = (n-tile nt = bid>>1, m-half mh = bid&1):
// 16 n-cols x 32 m-rows. 16 warps = 16 k-split groups (1 warp each).
// Thread: 1 m-row, 16 n (8 f32x2 accumulators). Weights SMEM k-row-major
// [k][16] -> 4 broadcast LDS.128 per k. 8 fma2 per activation LDG.
// ---------------------------------------------------------------------------
#define DEC_SMEM ((KD1*16 + DM*16 + 16*16*32) * 4)

__device__ __forceinline__ void dec_seg(
    u64 acc[8], const float* __restrict__ src, const float* __restrict__ Ws,
    int k0, int nk, int moff)
{
    const float* s = src + moff;
    const ulonglong2* wp = (const ulonglong2*)(Ws + k0 * 16);
    float av[4];
#pragma unroll
    for (int kk = 0; kk < 4; kk++) av[kk] = s[64 * kk];

    for (int i = 0; i < nk; i += 4) {
        s += 256;
        float nv[4];
#pragma unroll
        for (int kk = 0; kk < 4; kk++) nv[kk] = s[64 * kk];  // prefetch (padded)
#pragma unroll
        for (int kk = 0; kk < 4; kk++) {
            u64 ad = pk2(av[kk], av[kk]);
            ulonglong2 w0 = wp[0], w1 = wp[1], w2 = wp[2], w3 = wp[3];
            wp += 4;
            fma2(acc[0], ad, w0.x); fma2(acc[1], ad, w0.y);
            fma2(acc[2], ad, w1.x); fma2(acc[3], ad, w1.y);
            fma2(acc[4], ad, w2.x); fma2(acc[5], ad, w2.y);
            fma2(acc[6], ad, w3.x); fma2(acc[7], ad, w3.y);
        }
#pragma unroll
        for (int kk = 0; kk < 4; kk++) av[kk] = nv[kk];
    }
}

__global__ __launch_bounds__(512) void dec_persistent_kernel(
    const float* __restrict__ Wd1, const float* __restrict__ bd1,
    const float* __restrict__ Wd2, const float* __restrict__ bd2,
    float* __restrict__ out)
{
    extern __shared__ float sm[];
    float* Ws1 = sm;                        // [KD1][16]
    float* Ws2 = sm + KD1 * 16;             // [DM][16]
    float* red = sm + (KD1 + DM) * 16;      // [16g][16n][32m]

    int tid = threadIdx.x;
    int bid = blockIdx.x;
    int nt  = bid >> 1;          // n-tile 0..65
    int mh  = bid & 1;           // m-half
    int n0  = nt * 16;

    // one-time: cache weight slices k-row-major [k][16]
    for (int i = tid; i < 16 * KD1; i += 512) {
        int k = i >> 4, n = i & 15;
        Ws1[i] = Wd1[(size_t)k * DM + n0 + n];
    }
    if (nt < 64) {
        for (int i = tid; i < 16 * DM; i += 512) {
            int k = i >> 4, n = i & 15;
            Ws2[i] = Wd2[(size_t)k * SS + n0 + n];
        }
    }
    {
        int i = bid * 512 + tid;
        if (i < SS * BATCH) g_sbufT[0][i] = 0.f;
        if (i < 256) { g_sbufT[0][SS * BATCH + i] = 0.f; g_sbufT[1][SS * BATCH + i] = 0.f; }
    }

    int g    = tid >> 5;             // k-split group = warp 0..15
    int lane = tid & 31;
    int moff = mh * 32 + lane;       // global batch row
    int en   = tid >> 5;             // epilogue n 0..15
    int em   = tid & 31;             // epilogue m 0..31

    float bv1 = bd1[n0 + en];
    float bv2 = (nt < 64) ? bd2[n0 + en] : 0.f;

    grid_sync(NBLK);

    for (int t = 0; t < TT; t++) {
        const float* sbT = g_sbufT[t & 1];
        const float* ctrl_base = g_ctrlT + t * HH * BATCH;

        // ---- layer 1: g_hdT = relu([ctrl_t | prev] @ Wd1 + bd1), K=1088
        {
            u64 acc[8] = {};
            if (g == 0) {
                dec_seg(acc, ctrl_base, Ws1, 0, 64, moff);      // k 0..63
                dec_seg(acc, sbT, Ws1, 64, 4, moff);            // k 64..67
            } else {
                int kb = g * 68;                                 // 16*68 = 1088
                dec_seg(acc, sbT + (kb - HH) * 64, Ws1, kb, 68, moff);
            }
#pragma unroll
            for (int p = 0; p < 8; p++) {
                float lo, hi; unpk2(acc[p], lo, hi);
                red[(g * 16 + 2 * p) * 32 + lane]     = lo;
                red[(g * 16 + 2 * p + 1) * 32 + lane] = hi;
            }
            __syncthreads();

            float v = bv1;
#pragma unroll
            for (int gg = 0; gg < 16; gg++)
                v += red[(gg * 16 + en) * 32 + em];
            g_hdT[(n0 + en) * 64 + mh * 32 + em] = fmaxf(v, 0.f);
        }
        grid_sync(NBLK);

        // ---- layer 2: out_t = g_hd @ Wd2 + bd2, K=1056
        if (nt < 64) {
            u64 acc[8] = {};
            int kb  = (g < 8) ? g * 68 : 544 + (g - 8) * 64;    // 8*68+8*64 = 1056
            int nk2 = (g < 8) ? 68 : 64;
            dec_seg(acc, g_hdT + kb * 64, Ws2, kb, nk2, moff);
#pragma unroll
            for (int p = 0; p < 8; p++) {
                float lo, hi; unpk2(acc[p], lo, hi);
                red[(g * 16 + 2 * p) * 32 + lane]     = lo;
                red[(g * 16 + 2 * p + 1) * 32 + lane] = hi;
            }
            __syncthreads();

            float v = bv2;
#pragma unroll
            for (int gg = 0; gg < 16; gg++)
                v += red[(gg * 16 + en) * 32 + em];
            int s = n0 + en;
            int m = mh * 32 + em;
            g_sbufT[(t + 1) & 1][s * 64 + m] = v;
            out[((size_t)m * SS + s) * TT + t] = v;
        }
        grid_sync(NBLK);
    }
}

// ---------------------------------------------------------------------------
extern "C" void kernel_launch(void* const* d_in, const int* in_sizes, int n_in,
                              void* d_out, int out_size)
{
    const float* x   = (const float*)d_in[0];
    const float* We1 = (const float*)d_in[1];
    const float* be1 = (const float*)d_in[2];
    const float* We2 = (const float*)d_in[3];
    const float* be2 = (const float*)d_in[4];
    const float* Wd1 = (const float*)d_in[5];
    const float* bd1 = (const float*)d_in[6];
    const float* Wd2 = (const float*)d_in[7];
    const float* bd2 = (const float*)d_in[8];
    float* out = (float*)d_out;

    cudaFuncSetAttribute(dec_persistent_kernel,
                         cudaFuncAttributeMaxDynamicSharedMemorySize, DEC_SMEM);

    transpose_x_kernel<<<dim3(TT / 32, SS / 32, BATCH), dim3(32, 8)>>>(x);
    enc_gemm_kernel<0><<<dim3((EM + 63) / 64, MROWS / 64), 256>>>(We1, be1);
    enc_gemm_kernel<1><<<dim3(1, MROWS / 64), 256>>>(We2, be2);

    dec_persistent_kernel<<<NBLK, 512, DEC_SMEM>>>(Wd1, bd1, Wd2, bd2, out);
}